// round 3
// baseline (speedup 1.0000x reference)
#include <cuda_runtime.h>
#include <math.h>

// Problem constants (fixed by reference)
#define Bc   8
#define Sc   4096
#define Dm   1024
#define DKc  128
#define DVc  128
#define Mc   256
#define BSc  32768          // B*S
#define SCALE 0.29730177875068026f   // 128^-0.25
#define MINV  0.0625f                // 256^-0.5
#define EPSC  1e-6f

// ---------------- scratch (device globals; no allocation allowed) -------------
__device__ float g_q[BSc * DKc];
__device__ float g_k[BSc * DKc];
__device__ float g_v[BSc * DVc];
__device__ float g_pk[(size_t)BSc * Mc];          // 33.5 MB
__device__ float g_rnk[BSc];
__device__ float g_omegaT[DKc * Mc];              // omegaT[k][m] = omega[m][k]
__device__ float g_kvpart[8 * 16 * 256 * 128];    // split-K partials for kv
__device__ float g_ksumpart[8 * 32 * 256];
__device__ float g_kv[8 * 256 * 128];
__device__ float g_ksum[8 * 256];
__device__ unsigned int g_gmax_key;

// order-preserving float<->uint encoding for exact atomicMax
__device__ __forceinline__ unsigned fenc(float f) {
    unsigned u = __float_as_uint(f);
    return (u & 0x80000000u) ? ~u : (u | 0x80000000u);
}
__device__ __forceinline__ float fdec(unsigned k) {
    unsigned u = (k & 0x80000000u) ? (k ^ 0x80000000u) : ~k;
    return __uint_as_float(u);
}

// ---------------- K0: reset global-max accumulator ----------------------------
__global__ void k_init() { g_gmax_key = 0u; }

// ---------------- K1: fused QKV projection GEMM -------------------------------
// C[32768, 384] = x[32768,1024] @ [Wq|Wk|Wv], +bias, q/k scaled.
// grid (256 row-tiles, 3 outputs), 128x128x16 tile, 256 thr, 8x8 per thread.
__global__ __launch_bounds__(256) void k_qkv(
    const float* __restrict__ x,
    const float* __restrict__ Wq, const float* __restrict__ bq,
    const float* __restrict__ Wk, const float* __restrict__ bk,
    const float* __restrict__ Wv, const float* __restrict__ bv)
{
    const int rt = blockIdx.x;
    const int cs = blockIdx.y;
    const float* W;  const float* bias;  float* out;  float osc;
    if (cs == 0)      { W = Wq; bias = bq; out = g_q; osc = SCALE; }
    else if (cs == 1) { W = Wk; bias = bk; out = g_k; osc = SCALE; }
    else              { W = Wv; bias = bv; out = g_v; osc = 1.0f; }

    __shared__ float As[128][17];
    __shared__ float Bs[16][128];
    float acc[8][8] = {};
    const int tid = threadIdx.x;
    const int tx = tid & 15, ty = tid >> 4;
    const int row0 = rt * 128;

    for (int k0 = 0; k0 < Dm; k0 += 16) {
        #pragma unroll
        for (int i = 0; i < 2; i++) {
            int idx = tid + i * 256;          // 512 float4 of A tile
            int m = idx >> 2, kg = idx & 3;
            float4 v4 = *(const float4*)&x[(size_t)(row0 + m) * Dm + k0 + kg * 4];
            As[m][kg * 4 + 0] = v4.x; As[m][kg * 4 + 1] = v4.y;
            As[m][kg * 4 + 2] = v4.z; As[m][kg * 4 + 3] = v4.w;
        }
        #pragma unroll
        for (int i = 0; i < 2; i++) {
            int idx = tid + i * 256;          // 512 float4 of B tile
            int kk = idx >> 5, c4 = idx & 31;
            *(float4*)&Bs[kk][c4 * 4] =
                *(const float4*)&W[(size_t)(k0 + kk) * 128 + c4 * 4];
        }
        __syncthreads();
        #pragma unroll
        for (int kk = 0; kk < 16; kk++) {
            float rA[8], rB[8];
            #pragma unroll
            for (int i = 0; i < 8; i++) rA[i] = As[ty * 8 + i][kk];
            float4 b0 = *(float4*)&Bs[kk][tx * 8];
            float4 b1 = *(float4*)&Bs[kk][tx * 8 + 4];
            rB[0]=b0.x; rB[1]=b0.y; rB[2]=b0.z; rB[3]=b0.w;
            rB[4]=b1.x; rB[5]=b1.y; rB[6]=b1.z; rB[7]=b1.w;
            #pragma unroll
            for (int i = 0; i < 8; i++)
                #pragma unroll
                for (int j = 0; j < 8; j++)
                    acc[i][j] = fmaf(rA[i], rB[j], acc[i][j]);
        }
        __syncthreads();
    }
    #pragma unroll
    for (int i = 0; i < 8; i++) {
        int r = row0 + ty * 8 + i;
        #pragma unroll
        for (int j = 0; j < 8; j++) {
            int c = tx * 8 + j;
            out[(size_t)r * 128 + c] = (acc[i][j] + bias[c]) * osc;
        }
    }
}

// ---------------- K1b: k row-norms + omega transpose --------------------------
__global__ __launch_bounds__(256) void k_aux(const float* __restrict__ omega)
{
    if (blockIdx.x < 4096) {
        int warp = threadIdx.x >> 5, lane = threadIdx.x & 31;
        int row = blockIdx.x * 8 + warp;
        const float* kr = &g_k[(size_t)row * DKc];
        float s = 0.f;
        #pragma unroll
        for (int i = 0; i < 4; i++) { float t = kr[lane + 32 * i]; s += t * t; }
        #pragma unroll
        for (int o = 16; o; o >>= 1) s += __shfl_xor_sync(0xFFFFFFFFu, s, o);
        if (!lane) g_rnk[row] = 0.5f * s;
    } else {
        int base = (blockIdx.x - 4096) * 1024 + threadIdx.x;
        #pragma unroll
        for (int i = 0; i < 4; i++) {
            int idx = base + i * 256;          // linear over omegaT [128][256]
            int kk = idx >> 8, m = idx & 255;
            g_omegaT[idx] = omega[m * DKc + kk];
        }
    }
}

// ---------------- K2: pk = k @ omegaT - rnk; global max -----------------------
// grid (256 row-tiles, 2 col-tiles of 128), tile 128x128x16.
__global__ __launch_bounds__(256) void k_pk()
{
    __shared__ float As[128][17];
    __shared__ float Bs[16][128];
    __shared__ float red[256];
    const int rt = blockIdx.x;
    const int n0 = blockIdx.y * 128;
    const int tid = threadIdx.x;
    const int tx = tid & 15, ty = tid >> 4;
    const int row0 = rt * 128;
    float acc[8][8] = {};

    for (int k0 = 0; k0 < DKc; k0 += 16) {
        #pragma unroll
        for (int i = 0; i < 2; i++) {
            int idx = tid + i * 256;
            int m = idx >> 2, kg = idx & 3;
            float4 v4 = *(const float4*)&g_k[(size_t)(row0 + m) * DKc + k0 + kg * 4];
            As[m][kg * 4 + 0] = v4.x; As[m][kg * 4 + 1] = v4.y;
            As[m][kg * 4 + 2] = v4.z; As[m][kg * 4 + 3] = v4.w;
        }
        #pragma unroll
        for (int i = 0; i < 2; i++) {
            int idx = tid + i * 256;
            int kk = idx >> 5, c4 = idx & 31;
            *(float4*)&Bs[kk][c4 * 4] =
                *(const float4*)&g_omegaT[(size_t)(k0 + kk) * Mc + n0 + c4 * 4];
        }
        __syncthreads();
        #pragma unroll
        for (int kk = 0; kk < 16; kk++) {
            float rA[8], rB[8];
            #pragma unroll
            for (int i = 0; i < 8; i++) rA[i] = As[ty * 8 + i][kk];
            float4 b0 = *(float4*)&Bs[kk][tx * 8];
            float4 b1 = *(float4*)&Bs[kk][tx * 8 + 4];
            rB[0]=b0.x; rB[1]=b0.y; rB[2]=b0.z; rB[3]=b0.w;
            rB[4]=b1.x; rB[5]=b1.y; rB[6]=b1.z; rB[7]=b1.w;
            #pragma unroll
            for (int i = 0; i < 8; i++)
                #pragma unroll
                for (int j = 0; j < 8; j++)
                    acc[i][j] = fmaf(rA[i], rB[j], acc[i][j]);
        }
        __syncthreads();
    }
    float lm = -3.4e38f;
    #pragma unroll
    for (int i = 0; i < 8; i++) {
        int r = row0 + ty * 8 + i;
        float rn = g_rnk[r];
        #pragma unroll
        for (int j = 0; j < 8; j++) {
            float vv = acc[i][j] - rn;
            lm = fmaxf(lm, vv);
            g_pk[(size_t)r * Mc + n0 + tx * 8 + j] = vv;
        }
    }
    red[tid] = lm;
    __syncthreads();
    for (int o = 128; o; o >>= 1) {
        if (tid < o) red[tid] = fmaxf(red[tid], red[tid + o]);
        __syncthreads();
    }
    if (tid == 0) atomicMax(&g_gmax_key, fenc(red[0]));
}

// ---------------- K3: ksum partials (deterministic) ---------------------------
// grid (32 s-tiles, 8 batches), 256 threads = 256 m-columns.
__global__ __launch_bounds__(256) void k_ksum()
{
    const int st = blockIdx.x, b = blockIdx.y;
    const float g = fdec(g_gmax_key);
    const int m = threadIdx.x;
    const float* base = &g_pk[((size_t)(b * Sc + st * 128)) * Mc + m];
    float s = 0.f;
    for (int ss = 0; ss < 128; ss++) s += expf(base[(size_t)ss * Mc] - g);
    g_ksumpart[(b * 32 + st) * Mc + m] = s * MINV;
}

// ---------------- K4: kv split-K partials -------------------------------------
// grid (16 s-tiles of 256, 4 m-tiles of 64, 8 batches). out tile [64m x 128dv].
__global__ __launch_bounds__(256) void k_kv()
{
    __shared__ float As[16][64];   // phi chunk [s-chunk][m]
    __shared__ float Bs[16][128];  // v chunk [s-chunk][dv]
    const int st = blockIdx.x, mt = blockIdx.y, b = blockIdx.z;
    const float g = fdec(g_gmax_key);
    const int s0 = st * 256, m0 = mt * 64;
    const int tid = threadIdx.x;
    const int ty = tid >> 5, tx = tid & 31;     // 8 m-groups x 32 dv-groups
    float acc[8][4] = {};

    for (int sc = 0; sc < 256; sc += 16) {
        #pragma unroll
        for (int i = 0; i < 4; i++) {
            int idx = tid + i * 256;           // 1024 elems of phi chunk
            int m = idx & 63, ss = idx >> 6;
            float pkv = g_pk[((size_t)(b * Sc + s0 + sc + ss)) * Mc + m0 + m];
            As[ss][m] = expf(pkv - g) * MINV;
        }
        #pragma unroll
        for (int i = 0; i < 2; i++) {
            int idx = tid + i * 256;           // 512 float4 of v chunk
            int c4 = idx & 31, ss = idx >> 5;
            *(float4*)&Bs[ss][c4 * 4] =
                *(const float4*)&g_v[((size_t)(b * Sc + s0 + sc + ss)) * DVc + c4 * 4];
        }
        __syncthreads();
        #pragma unroll
        for (int kk = 0; kk < 16; kk++) {
            float rA[8];
            #pragma unroll
            for (int i = 0; i < 8; i++) rA[i] = As[kk][ty * 8 + i];
            float4 b4 = *(float4*)&Bs[kk][tx * 4];
            float rB[4] = { b4.x, b4.y, b4.z, b4.w };
            #pragma unroll
            for (int i = 0; i < 8; i++)
                #pragma unroll
                for (int j = 0; j < 4; j++)
                    acc[i][j] = fmaf(rA[i], rB[j], acc[i][j]);
        }
        __syncthreads();
    }
    #pragma unroll
    for (int i = 0; i < 8; i++)
        #pragma unroll
        for (int j = 0; j < 4; j++)
            g_kvpart[((size_t)((b * 16 + st) * Mc + m0 + ty * 8 + i)) * DVc + tx * 4 + j]
                = acc[i][j];
}

// ---------------- K5: reduce partials -----------------------------------------
__global__ __launch_bounds__(256) void k_reduce()
{
    int idx = blockIdx.x * 256 + threadIdx.x;
    if (idx < 8 * 256 * 128) {
        int b = idx >> 15;
        int o = idx & 32767;
        size_t base = (size_t)b * 16 * 32768 + o;
        float s = 0.f;
        #pragma unroll
        for (int st = 0; st < 16; st++) s += g_kvpart[base + (size_t)st * 32768];
        g_kv[idx] = s;
    } else if (idx < 8 * 256 * 128 + 2048) {
        int j = idx - 262144;
        int b = j >> 8, m = j & 255;
        float s = 0.f;
        #pragma unroll
        for (int st = 0; st < 32; st++) s += g_ksumpart[(b * 32 + st) * Mc + m];
        g_ksum[j] = s;
    }
}

// ---------------- K6: fused phi_q + attention output --------------------------
// grid (64 s-tiles of 64, 8 batches). Dynamic smem ~113 KB.
#define K6_SMEM_FLOATS (8192 + 4096 + 64 * 260)
__global__ __launch_bounds__(256) void k_out(float* __restrict__ out)
{
    extern __shared__ float sm[];
    float* q_s = sm;                 // [64][128] then aliased as Bs2 [16][128]
    float* aux = sm + 8192;          // Bs1 [16][256] then red/ksum/rmax/den
    float* phi = sm + 8192 + 4096;   // [64][260]

    const int stile = blockIdx.x, b = blockIdx.y;
    const int s0 = stile * 64;
    const int tid = threadIdx.x;
    const int ty = tid >> 5, tx = tid & 31;

    // load q tile [64][128]
    #pragma unroll
    for (int i = 0; i < 8; i++) {
        int idx = tid + i * 256;             // 2048 float4
        int c4 = idx & 31, r = idx >> 5;
        *(float4*)&q_s[r * 128 + c4 * 4] =
            *(const float4*)&g_q[((size_t)(b * Sc + s0 + r)) * DKc + c4 * 4];
    }
    __syncthreads();

    // stage 1: proj[64][256] = q @ omegaT   (ty: 8 row-groups x8, tx: 32 col-groups x8)
    float a1[8][8] = {};
    for (int k0 = 0; k0 < DKc; k0 += 16) {
        float* Bs1 = aux;
        #pragma unroll
        for (int i = 0; i < 4; i++) {
            int idx = tid + i * 256;         // 1024 float4 of omegaT chunk
            int c4 = idx & 63, kk = idx >> 6;
            *(float4*)&Bs1[kk * 256 + c4 * 4] =
                *(const float4*)&g_omegaT[(size_t)(k0 + kk) * Mc + c4 * 4];
        }
        __syncthreads();
        #pragma unroll
        for (int kk = 0; kk < 16; kk++) {
            float rA[8];
            #pragma unroll
            for (int i = 0; i < 8; i++) rA[i] = q_s[(ty * 8 + i) * 128 + k0 + kk];
            float4 b0 = *(float4*)&Bs1[kk * 256 + tx * 8];
            float4 b1 = *(float4*)&Bs1[kk * 256 + tx * 8 + 4];
            float rB[8] = { b0.x, b0.y, b0.z, b0.w, b1.x, b1.y, b1.z, b1.w };
            #pragma unroll
            for (int i = 0; i < 8; i++)
                #pragma unroll
                for (int j = 0; j < 8; j++)
                    a1[i][j] = fmaf(rA[i], rB[j], a1[i][j]);
        }
        __syncthreads();
    }
    #pragma unroll
    for (int i = 0; i < 8; i++) {
        int r = ty * 8 + i;
        *(float4*)&phi[r * 260 + tx * 8]     = make_float4(a1[i][0], a1[i][1], a1[i][2], a1[i][3]);
        *(float4*)&phi[r * 260 + tx * 8 + 4] = make_float4(a1[i][4], a1[i][5], a1[i][6], a1[i][7]);
    }
    __syncthreads();

    // row max + ksum load
    float* red    = aux;         // 256
    float* ksum_s = aux + 256;   // 256
    float* rmax   = aux + 512;   // 64
    float* denred = aux + 576;   // 256
    float* den    = aux + 832;   // 64
    {
        int row = tid & 63, seg = tid >> 6;
        const float* pr = &phi[row * 260 + seg * 64];
        float pm = -3.4e38f;
        #pragma unroll
        for (int i = 0; i < 64; i++) pm = fmaxf(pm, pr[i]);
        red[tid] = pm;
        ksum_s[tid] = g_ksum[b * Mc + tid];
    }
    __syncthreads();
    if (tid < 64)
        rmax[tid] = fmaxf(fmaxf(red[tid], red[tid + 64]),
                          fmaxf(red[tid + 128], red[tid + 192]));
    __syncthreads();
    // exp + den partial
    {
        int row = tid & 63, seg = tid >> 6;
        float rm = rmax[row];
        float* pr = &phi[row * 260 + seg * 64];
        const float* ks = &ksum_s[seg * 64];
        float ds = 0.f;
        #pragma unroll
        for (int i = 0; i < 64; i++) {
            float p = expf(pr[i] - rm) * MINV;
            pr[i] = p;
            ds = fmaf(p, ks[i], ds);
        }
        denred[tid] = ds;
    }
    __syncthreads();
    if (tid < 64)
        den[tid] = denred[tid] + denred[tid + 64] + denred[tid + 128]
                 + denred[tid + 192] + EPSC;
    __syncthreads();

    // stage 2: num[64][128] = phi @ kv   (ty: 8 row-groups x8, tx: 32 col-groups x4)
    float a2[8][4] = {};
    float* Bs2 = q_s;
    for (int k0 = 0; k0 < Mc; k0 += 16) {
        #pragma unroll
        for (int i = 0; i < 2; i++) {
            int idx = tid + i * 256;         // 512 float4 of kv chunk
            int c4 = idx & 31, kk = idx >> 5;
            *(float4*)&Bs2[kk * 128 + c4 * 4] =
                *(const float4*)&g_kv[((size_t)(b * Mc + k0 + kk)) * DVc + c4 * 4];
        }
        __syncthreads();
        #pragma unroll
        for (int kk = 0; kk < 16; kk++) {
            float rA[8];
            #pragma unroll
            for (int i = 0; i < 8; i++) rA[i] = phi[(ty * 8 + i) * 260 + k0 + kk];
            float4 b4 = *(float4*)&Bs2[kk * 128 + tx * 4];
            float rB[4] = { b4.x, b4.y, b4.z, b4.w };
            #pragma unroll
            for (int i = 0; i < 8; i++)
                #pragma unroll
                for (int j = 0; j < 4; j++)
                    a2[i][j] = fmaf(rA[i], rB[j], a2[i][j]);
        }
        __syncthreads();
    }
    #pragma unroll
    for (int i = 0; i < 8; i++) {
        int r = ty * 8 + i;
        float invd = 1.0f / den[r];
        float4 o4 = make_float4(a2[i][0] * invd, a2[i][1] * invd,
                                a2[i][2] * invd, a2[i][3] * invd);
        *(float4*)&out[((size_t)(b * Sc + s0 + r)) * DVc + tx * 4] = o4;
    }
}

// ---------------- launch ------------------------------------------------------
extern "C" void kernel_launch(void* const* d_in, const int* in_sizes, int n_in,
                              void* d_out, int out_size)
{
    const float* x     = (const float*)d_in[0];
    const float* Wq    = (const float*)d_in[1];
    const float* bq    = (const float*)d_in[2];
    const float* Wk    = (const float*)d_in[3];
    const float* bk    = (const float*)d_in[4];
    const float* Wv    = (const float*)d_in[5];
    const float* bv    = (const float*)d_in[6];
    const float* omega = (const float*)d_in[7];
    float* out = (float*)d_out;

    // idempotent; persists across calls (also called on the pre-capture run)
    cudaFuncSetAttribute(k_out, cudaFuncAttributeMaxDynamicSharedMemorySize,
                         K6_SMEM_FLOATS * 4);

    k_init<<<1, 1>>>();
    k_qkv<<<dim3(256, 3), 256>>>(x, Wq, bq, Wk, bk, Wv, bv);
    k_aux<<<4128, 256>>>(omega);
    k_pk<<<dim3(256, 2), 256>>>();
    k_ksum<<<dim3(32, 8), 256>>>();
    k_kv<<<dim3(16, 4, 8), 256>>>();
    k_reduce<<<1032, 256>>>();
    k_out<<<dim3(64, 8), 256, K6_SMEM_FLOATS * 4>>>(out);
}

// round 6
// speedup vs baseline: 1.7799x; 1.7799x over previous
#include <cuda_runtime.h>
#include <cuda_bf16.h>
#include <math.h>

// Problem constants (fixed by reference)
#define Bc   8
#define Sc   4096
#define Dm   1024
#define DKc  128
#define DVc  128
#define Mc   256
#define BSc  32768          // B*S
#define SCALE 0.29730177875068026f   // 128^-0.25
#define MINV  0.0625f                // 256^-0.5
#define EPSC  1e-6f

// ---------------- scratch (device globals; no allocation allowed) -------------
__device__ float g_q[BSc * DKc];
__device__ float g_k[BSc * DKc];
__device__ float g_v[BSc * DVc];
__device__ float g_pk[(size_t)BSc * Mc];          // 33.5 MB
__device__ float g_rnk[BSc];
__device__ float g_omegaT[DKc * Mc];              // omegaT[k][m] = omega[m][k]
__device__ float g_kvpart[8 * 16 * 256 * 128];    // split-K partials for kv
__device__ float g_ksumpart[8 * 32 * 256];
__device__ float g_kv[8 * 256 * 128];
__device__ float g_ksum[8 * 256];
__device__ unsigned int g_gmax_key;

// bf16 hi/lo split operands for mma.sync QKV GEMM
__device__ __align__(16) __nv_bfloat16 g_xh[(size_t)BSc * Dm];   // 64 MB
__device__ __align__(16) __nv_bfloat16 g_xl[(size_t)BSc * Dm];   // 64 MB
// transposed, scaled, split weights: [6 tiles][128 n][1024 k]
// tiles: 0=Wq_hi 1=Wq_lo 2=Wk_hi 3=Wk_lo 4=Wv_hi 5=Wv_lo
__device__ __align__(16) __nv_bfloat16 g_wt[6 * 128 * 1024];
__device__ __align__(16) float g_bias[384];       // pre-scaled biases [q|k|v]

// order-preserving float<->uint encoding for exact atomicMax
__device__ __forceinline__ unsigned fenc(float f) {
    unsigned u = __float_as_uint(f);
    return (u & 0x80000000u) ? ~u : (u | 0x80000000u);
}
__device__ __forceinline__ float fdec(unsigned k) {
    unsigned u = (k & 0x80000000u) ? (k ^ 0x80000000u) : ~k;
    return __uint_as_float(u);
}

__device__ __forceinline__ unsigned smem_u32(const void* p) {
    unsigned a;
    asm("{ .reg .u64 t; cvta.to.shared.u64 t, %1; cvt.u32.u64 %0, t; }"
        : "=r"(a) : "l"(p));
    return a;
}
__device__ __forceinline__ void cp16(unsigned dst, const void* src) {
    asm volatile("cp.async.cg.shared.global [%0], [%1], 16;"
                 :: "r"(dst), "l"(src) : "memory");
}
#define LDSM4(r, addr) asm volatile( \
    "ldmatrix.sync.aligned.m8n8.x4.shared.b16 {%0,%1,%2,%3}, [%4];" \
    : "=r"((r)[0]), "=r"((r)[1]), "=r"((r)[2]), "=r"((r)[3]) : "r"(addr))
#define MMA16816(d, a, b) asm volatile( \
    "mma.sync.aligned.m16n8k16.row.col.f32.bf16.bf16.f32 " \
    "{%0,%1,%2,%3}, {%4,%5,%6,%7}, {%8,%9}, {%0,%1,%2,%3};" \
    : "+f"((d)[0]), "+f"((d)[1]), "+f"((d)[2]), "+f"((d)[3]) \
    : "r"((a)[0]), "r"((a)[1]), "r"((a)[2]), "r"((a)[3]), \
      "r"((b)[0]), "r"((b)[1]))

// ---------------- K0: reset global-max accumulator ----------------------------
__global__ void k_init() { g_gmax_key = 0u; }

// ---------------- K_split: x -> xh + xl (bf16 hi/lo) --------------------------
__global__ __launch_bounds__(256) void k_split(const float* __restrict__ x)
{
    size_t i = ((size_t)blockIdx.x * 256 + threadIdx.x) * 4;
    float4 v = *(const float4*)&x[i];
    __nv_bfloat16 h0 = __float2bfloat16(v.x);
    __nv_bfloat16 h1 = __float2bfloat16(v.y);
    __nv_bfloat16 h2 = __float2bfloat16(v.z);
    __nv_bfloat16 h3 = __float2bfloat16(v.w);
    __nv_bfloat16 l0 = __float2bfloat16(v.x - __bfloat162float(h0));
    __nv_bfloat16 l1 = __float2bfloat16(v.y - __bfloat162float(h1));
    __nv_bfloat16 l2 = __float2bfloat16(v.z - __bfloat162float(h2));
    __nv_bfloat16 l3 = __float2bfloat16(v.w - __bfloat162float(h3));
    uint2 hh, ll;
    hh.x = (unsigned)__bfloat16_as_ushort(h0) | ((unsigned)__bfloat16_as_ushort(h1) << 16);
    hh.y = (unsigned)__bfloat16_as_ushort(h2) | ((unsigned)__bfloat16_as_ushort(h3) << 16);
    ll.x = (unsigned)__bfloat16_as_ushort(l0) | ((unsigned)__bfloat16_as_ushort(l1) << 16);
    ll.y = (unsigned)__bfloat16_as_ushort(l2) | ((unsigned)__bfloat16_as_ushort(l3) << 16);
    *(uint2*)&g_xh[i] = hh;
    *(uint2*)&g_xl[i] = ll;
}

// ---------------- K_wprep: transpose + scale + split weights, biases ----------
__global__ __launch_bounds__(256) void k_wprep(
    const float* __restrict__ Wq, const float* __restrict__ bq,
    const float* __restrict__ Wk, const float* __restrict__ bk,
    const float* __restrict__ Wv, const float* __restrict__ bv)
{
    int idx = blockIdx.x * 256 + threadIdx.x;
    if (idx < 393216) {
        int out = idx >> 17;
        int r = idx & 131071;
        int n = r >> 10, kk = r & 1023;
        const float* W = (out == 0) ? Wq : (out == 1) ? Wk : Wv;
        float osc = (out == 2) ? 1.0f : SCALE;
        float w = W[(size_t)kk * 128 + n] * osc;
        __nv_bfloat16 h = __float2bfloat16(w);
        __nv_bfloat16 l = __float2bfloat16(w - __bfloat162float(h));
        g_wt[(size_t)(out * 2) * 131072 + (size_t)n * 1024 + kk] = h;
        g_wt[(size_t)(out * 2 + 1) * 131072 + (size_t)n * 1024 + kk] = l;
    } else if (idx < 393216 + 384) {
        int j = idx - 393216;
        int out = j >> 7, c = j & 127;
        const float* bias = (out == 0) ? bq : (out == 1) ? bk : bv;
        g_bias[j] = bias[c] * ((out == 2) ? 1.0f : SCALE);
    }
}

// ---------------- K1: QKV GEMM via mma.sync bf16 (3-product split) ------------
// grid (3 outs, 256 row-tiles); each CTA computes [128 rows x 128 cols].
// SMEM: 2 stages x {xh,xl,wh,wl}[128][40] halves + bias[128] floats.
#define QS_ARR   10240              // bytes per [128][40] bf16 array
#define QS_STAGE 40960
#define QS_BIAS  81920
#define QS_TOTAL 82432

__global__ __launch_bounds__(256) void k_qkv_mma()
{
    extern __shared__ __align__(16) char smem[];
    const unsigned sb = smem_u32(smem);
    float* bias_s = (float*)(smem + QS_BIAS);

    const int tid = threadIdx.x;
    const int wid = tid >> 5, lane = tid & 31;
    const int wr = wid >> 2, wc = wid & 3;      // warp tile: 64 rows x 32 cols
    const int cs = blockIdx.x;                  // 0=q 1=k 2=v
    const int row0 = blockIdx.y * 128;

    if (tid < 128) bias_s[tid] = g_bias[cs * 128 + tid];

    const size_t xoff0 = (size_t)row0 * 1024;
    const size_t w0off = (size_t)(cs * 2) * 131072;
    const size_t w1off = (size_t)(cs * 2 + 1) * 131072;

    // ---- chunk loader: 4 arrays x 128 rows x 64B via cp.async ----
    auto load_chunk = [&](int c, int buf) {
        const int k0 = c * 32;
        const unsigned base = sb + buf * QS_STAGE;
        #pragma unroll
        for (int i = 0; i < 8; i++) {
            const int arr = i >> 1;             // compile-time per unrolled i
            int rem = ((i & 1) << 8) + tid;     // 0..511
            int r = rem >> 2, j = rem & 3;
            const char* s;
            if (arr == 0)      s = (const char*)(g_xh + xoff0 + k0);
            else if (arr == 1) s = (const char*)(g_xl + xoff0 + k0);
            else if (arr == 2) s = (const char*)(g_wt + w0off + k0);
            else               s = (const char*)(g_wt + w1off + k0);
            cp16(base + arr * QS_ARR + r * 80 + j * 16,
                 s + (size_t)r * 2048 + j * 16);
        }
        asm volatile("cp.async.commit_group;" ::: "memory");
    };

    float acc[4][4][4] = {};

    // ldmatrix address bases (byte offsets within an array)
    const int arow0 = ((wr * 64 + (lane & 15)) * 40 + ((lane >> 4) << 3)) * 2;
    const int brow0 = ((wc * 32 + ((lane >> 4) << 3) + (lane & 7)) * 40
                       + (((lane >> 3) & 1) << 3)) * 2;

    load_chunk(0, 0);
    for (int c = 0; c < 32; c++) {
        if (c + 1 < 32) {
            load_chunk(c + 1, (c + 1) & 1);
            asm volatile("cp.async.wait_group 1;" ::: "memory");
        } else {
            asm volatile("cp.async.wait_group 0;" ::: "memory");
        }
        __syncthreads();

        const unsigned ab  = sb + (c & 1) * QS_STAGE;          // xh
        const unsigned alb = ab + QS_ARR;                      // xl
        const unsigned whb = ab + 2 * QS_ARR;                  // wh
        const unsigned wlb = ab + 3 * QS_ARR;                  // wl

        #pragma unroll
        for (int ks = 0; ks < 2; ks++) {
            const int kb = ks * 32;                            // 16 halves
            unsigned ah[4][4], al[4][4], bh[8], bl[8];
            #pragma unroll
            for (int mt = 0; mt < 4; mt++) {
                LDSM4(ah[mt], ab  + arow0 + kb + mt * 1280);
                LDSM4(al[mt], alb + arow0 + kb + mt * 1280);
            }
            #pragma unroll
            for (int p = 0; p < 2; p++) {
                LDSM4(&bh[p * 4], whb + brow0 + kb + p * 1280);
                LDSM4(&bl[p * 4], wlb + brow0 + kb + p * 1280);
            }
            #pragma unroll
            for (int mt = 0; mt < 4; mt++)
                #pragma unroll
                for (int nt = 0; nt < 4; nt++) {
                    MMA16816(acc[mt][nt], ah[mt], &bh[nt * 2]);
                    MMA16816(acc[mt][nt], ah[mt], &bl[nt * 2]);
                    MMA16816(acc[mt][nt], al[mt], &bh[nt * 2]);
                }
        }
        __syncthreads();
    }

    // ---- epilogue: +bias -> global ----
    float* dst = (cs == 0) ? g_q : (cs == 1) ? g_k : g_v;
    #pragma unroll
    for (int mt = 0; mt < 4; mt++) {
        int rm = row0 + wr * 64 + mt * 16 + (lane >> 2);
        #pragma unroll
        for (int nt = 0; nt < 4; nt++) {
            int col = wc * 32 + nt * 8 + (lane & 3) * 2;
            float b0 = bias_s[col], b1 = bias_s[col + 1];
            *(float2*)&dst[(size_t)rm * 128 + col] =
                make_float2(acc[mt][nt][0] + b0, acc[mt][nt][1] + b1);
            *(float2*)&dst[(size_t)(rm + 8) * 128 + col] =
                make_float2(acc[mt][nt][2] + b0, acc[mt][nt][3] + b1);
        }
    }
}

// ---------------- K1b: k row-norms + omega transpose --------------------------
__global__ __launch_bounds__(256) void k_aux(const float* __restrict__ omega)
{
    if (blockIdx.x < 4096) {
        int warp = threadIdx.x >> 5, lane = threadIdx.x & 31;
        int row = blockIdx.x * 8 + warp;
        const float* kr = &g_k[(size_t)row * DKc];
        float s = 0.f;
        #pragma unroll
        for (int i = 0; i < 4; i++) { float t = kr[lane + 32 * i]; s += t * t; }
        #pragma unroll
        for (int o = 16; o; o >>= 1) s += __shfl_xor_sync(0xFFFFFFFFu, s, o);
        if (!lane) g_rnk[row] = 0.5f * s;
    } else {
        int base = (blockIdx.x - 4096) * 1024 + threadIdx.x;
        #pragma unroll
        for (int i = 0; i < 4; i++) {
            int idx = base + i * 256;          // linear over omegaT [128][256]
            int kk = idx >> 8, m = idx & 255;
            g_omegaT[idx] = omega[m * DKc + kk];
        }
    }
}

// ---------------- K2: pk = k @ omegaT - rnk; global max -----------------------
__global__ __launch_bounds__(256) void k_pk()
{
    __shared__ float As[128][17];
    __shared__ float Bs[16][128];
    __shared__ float red[256];
    const int rt = blockIdx.x;
    const int n0 = blockIdx.y * 128;
    const int tid = threadIdx.x;
    const int tx = tid & 15, ty = tid >> 4;
    const int row0 = rt * 128;
    float acc[8][8] = {};

    for (int k0 = 0; k0 < DKc; k0 += 16) {
        #pragma unroll
        for (int i = 0; i < 2; i++) {
            int idx = tid + i * 256;
            int m = idx >> 2, kg = idx & 3;
            float4 v4 = *(const float4*)&g_k[(size_t)(row0 + m) * DKc + k0 + kg * 4];
            As[m][kg * 4 + 0] = v4.x; As[m][kg * 4 + 1] = v4.y;
            As[m][kg * 4 + 2] = v4.z; As[m][kg * 4 + 3] = v4.w;
        }
        #pragma unroll
        for (int i = 0; i < 2; i++) {
            int idx = tid + i * 256;
            int kk = idx >> 5, c4 = idx & 31;
            *(float4*)&Bs[kk][c4 * 4] =
                *(const float4*)&g_omegaT[(size_t)(k0 + kk) * Mc + n0 + c4 * 4];
        }
        __syncthreads();
        #pragma unroll
        for (int kk = 0; kk < 16; kk++) {
            float rA[8], rB[8];
            #pragma unroll
            for (int i = 0; i < 8; i++) rA[i] = As[ty * 8 + i][kk];
            float4 b0 = *(float4*)&Bs[kk][tx * 8];
            float4 b1 = *(float4*)&Bs[kk][tx * 8 + 4];
            rB[0]=b0.x; rB[1]=b0.y; rB[2]=b0.z; rB[3]=b0.w;
            rB[4]=b1.x; rB[5]=b1.y; rB[6]=b1.z; rB[7]=b1.w;
            #pragma unroll
            for (int i = 0; i < 8; i++)
                #pragma unroll
                for (int j = 0; j < 8; j++)
                    acc[i][j] = fmaf(rA[i], rB[j], acc[i][j]);
        }
        __syncthreads();
    }
    float lm = -3.4e38f;
    #pragma unroll
    for (int i = 0; i < 8; i++) {
        int r = row0 + ty * 8 + i;
        float rn = g_rnk[r];
        #pragma unroll
        for (int j = 0; j < 8; j++) {
            float vv = acc[i][j] - rn;
            lm = fmaxf(lm, vv);
            g_pk[(size_t)r * Mc + n0 + tx * 8 + j] = vv;
        }
    }
    red[tid] = lm;
    __syncthreads();
    for (int o = 128; o; o >>= 1) {
        if (tid < o) red[tid] = fmaxf(red[tid], red[tid + o]);
        __syncthreads();
    }
    if (tid == 0) atomicMax(&g_gmax_key, fenc(red[0]));
}

// ---------------- K3: ksum partials (deterministic) ---------------------------
__global__ __launch_bounds__(256) void k_ksum()
{
    const int st = blockIdx.x, b = blockIdx.y;
    const float g = fdec(g_gmax_key);
    const int m = threadIdx.x;
    const float* base = &g_pk[((size_t)(b * Sc + st * 128)) * Mc + m];
    float s = 0.f;
    for (int ss = 0; ss < 128; ss++) s += expf(base[(size_t)ss * Mc] - g);
    g_ksumpart[(b * 32 + st) * Mc + m] = s * MINV;
}

// ---------------- K4: kv split-K partials -------------------------------------
__global__ __launch_bounds__(256) void k_kv()
{
    __shared__ float As[16][64];
    __shared__ float Bs[16][128];
    const int st = blockIdx.x, mt = blockIdx.y, b = blockIdx.z;
    const float g = fdec(g_gmax_key);
    const int s0 = st * 256, m0 = mt * 64;
    const int tid = threadIdx.x;
    const int ty = tid >> 5, tx = tid & 31;
    float acc[8][4] = {};

    for (int sc = 0; sc < 256; sc += 16) {
        #pragma unroll
        for (int i = 0; i < 4; i++) {
            int idx = tid + i * 256;
            int m = idx & 63, ss = idx >> 6;
            float pkv = g_pk[((size_t)(b * Sc + s0 + sc + ss)) * Mc + m0 + m];
            As[ss][m] = expf(pkv - g) * MINV;
        }
        #pragma unroll
        for (int i = 0; i < 2; i++) {
            int idx = tid + i * 256;
            int c4 = idx & 31, ss = idx >> 5;
            *(float4*)&Bs[ss][c4 * 4] =
                *(const float4*)&g_v[((size_t)(b * Sc + s0 + sc + ss)) * DVc + c4 * 4];
        }
        __syncthreads();
        #pragma unroll
        for (int kk = 0; kk < 16; kk++) {
            float rA[8];
            #pragma unroll
            for (int i = 0; i < 8; i++) rA[i] = As[kk][ty * 8 + i];
            float4 b4 = *(float4*)&Bs[kk][tx * 4];
            float rB[4] = { b4.x, b4.y, b4.z, b4.w };
            #pragma unroll
            for (int i = 0; i < 8; i++)
                #pragma unroll
                for (int j = 0; j < 4; j++)
                    acc[i][j] = fmaf(rA[i], rB[j], acc[i][j]);
        }
        __syncthreads();
    }
    #pragma unroll
    for (int i = 0; i < 8; i++)
        #pragma unroll
        for (int j = 0; j < 4; j++)
            g_kvpart[((size_t)((b * 16 + st) * Mc + m0 + ty * 8 + i)) * DVc + tx * 4 + j]
                = acc[i][j];
}

// ---------------- K5: reduce partials -----------------------------------------
__global__ __launch_bounds__(256) void k_reduce()
{
    int idx = blockIdx.x * 256 + threadIdx.x;
    if (idx < 8 * 256 * 128) {
        int b = idx >> 15;
        int o = idx & 32767;
        size_t base = (size_t)b * 16 * 32768 + o;
        float s = 0.f;
        #pragma unroll
        for (int st = 0; st < 16; st++) s += g_kvpart[base + (size_t)st * 32768];
        g_kv[idx] = s;
    } else if (idx < 8 * 256 * 128 + 2048) {
        int j = idx - 262144;
        int b = j >> 8, m = j & 255;
        float s = 0.f;
        #pragma unroll
        for (int st = 0; st < 32; st++) s += g_ksumpart[(b * 32 + st) * Mc + m];
        g_ksum[j] = s;
    }
}

// ---------------- K6: fused phi_q + attention output --------------------------
#define K6_SMEM_FLOATS (8192 + 4096 + 64 * 260)
__global__ __launch_bounds__(256) void k_out(float* __restrict__ out)
{
    extern __shared__ float sm[];
    float* q_s = sm;
    float* aux = sm + 8192;
    float* phi = sm + 8192 + 4096;

    const int stile = blockIdx.x, b = blockIdx.y;
    const int s0 = stile * 64;
    const int tid = threadIdx.x;
    const int ty = tid >> 5, tx = tid & 31;

    #pragma unroll
    for (int i = 0; i < 8; i++) {
        int idx = tid + i * 256;
        int c4 = idx & 31, r = idx >> 5;
        *(float4*)&q_s[r * 128 + c4 * 4] =
            *(const float4*)&g_q[((size_t)(b * Sc + s0 + r)) * DKc + c4 * 4];
    }
    __syncthreads();

    float a1[8][8] = {};
    for (int k0 = 0; k0 < DKc; k0 += 16) {
        float* Bs1 = aux;
        #pragma unroll
        for (int i = 0; i < 4; i++) {
            int idx = tid + i * 256;
            int c4 = idx & 63, kk = idx >> 6;
            *(float4*)&Bs1[kk * 256 + c4 * 4] =
                *(const float4*)&g_omegaT[(size_t)(k0 + kk) * Mc + c4 * 4];
        }
        __syncthreads();
        #pragma unroll
        for (int kk = 0; kk < 16; kk++) {
            float rA[8];
            #pragma unroll
            for (int i = 0; i < 8; i++) rA[i] = q_s[(ty * 8 + i) * 128 + k0 + kk];
            float4 b0 = *(float4*)&Bs1[kk * 256 + tx * 8];
            float4 b1 = *(float4*)&Bs1[kk * 256 + tx * 8 + 4];
            float rB[8] = { b0.x, b0.y, b0.z, b0.w, b1.x, b1.y, b1.z, b1.w };
            #pragma unroll
            for (int i = 0; i < 8; i++)
                #pragma unroll
                for (int j = 0; j < 8; j++)
                    a1[i][j] = fmaf(rA[i], rB[j], a1[i][j]);
        }
        __syncthreads();
    }
    #pragma unroll
    for (int i = 0; i < 8; i++) {
        int r = ty * 8 + i;
        *(float4*)&phi[r * 260 + tx * 8]     = make_float4(a1[i][0], a1[i][1], a1[i][2], a1[i][3]);
        *(float4*)&phi[r * 260 + tx * 8 + 4] = make_float4(a1[i][4], a1[i][5], a1[i][6], a1[i][7]);
    }
    __syncthreads();

    float* red    = aux;
    float* ksum_s = aux + 256;
    float* rmax   = aux + 512;
    float* denred = aux + 576;
    float* den    = aux + 832;
    {
        int row = tid & 63, seg = tid >> 6;
        const float* pr = &phi[row * 260 + seg * 64];
        float pm = -3.4e38f;
        #pragma unroll
        for (int i = 0; i < 64; i++) pm = fmaxf(pm, pr[i]);
        red[tid] = pm;
        ksum_s[tid] = g_ksum[b * Mc + tid];
    }
    __syncthreads();
    if (tid < 64)
        rmax[tid] = fmaxf(fmaxf(red[tid], red[tid + 64]),
                          fmaxf(red[tid + 128], red[tid + 192]));
    __syncthreads();
    {
        int row = tid & 63, seg = tid >> 6;
        float rm = rmax[row];
        float* pr = &phi[row * 260 + seg * 64];
        const float* ks = &ksum_s[seg * 64];
        float ds = 0.f;
        #pragma unroll
        for (int i = 0; i < 64; i++) {
            float p = expf(pr[i] - rm) * MINV;
            pr[i] = p;
            ds = fmaf(p, ks[i], ds);
        }
        denred[tid] = ds;
    }
    __syncthreads();
    if (tid < 64)
        den[tid] = denred[tid] + denred[tid + 64] + denred[tid + 128]
                 + denred[tid + 192] + EPSC;
    __syncthreads();

    float a2[8][4] = {};
    float* Bs2 = q_s;
    for (int k0 = 0; k0 < Mc; k0 += 16) {
        #pragma unroll
        for (int i = 0; i < 2; i++) {
            int idx = tid + i * 256;
            int c4 = idx & 31, kk = idx >> 5;
            *(float4*)&Bs2[kk * 128 + c4 * 4] =
                *(const float4*)&g_kv[((size_t)(b * Mc + k0 + kk)) * DVc + c4 * 4];
        }
        __syncthreads();
        #pragma unroll
        for (int kk = 0; kk < 16; kk++) {
            float rA[8];
            #pragma unroll
            for (int i = 0; i < 8; i++) rA[i] = phi[(ty * 8 + i) * 260 + k0 + kk];
            float4 b4 = *(float4*)&Bs2[kk * 128 + tx * 4];
            float rB[4] = { b4.x, b4.y, b4.z, b4.w };
            #pragma unroll
            for (int i = 0; i < 8; i++)
                #pragma unroll
                for (int j = 0; j < 4; j++)
                    a2[i][j] = fmaf(rA[i], rB[j], a2[i][j]);
        }
        __syncthreads();
    }
    #pragma unroll
    for (int i = 0; i < 8; i++) {
        int r = ty * 8 + i;
        float invd = 1.0f / den[r];
        float4 o4 = make_float4(a2[i][0] * invd, a2[i][1] * invd,
                                a2[i][2] * invd, a2[i][3] * invd);
        *(float4*)&out[((size_t)(b * Sc + s0 + r)) * DVc + tx * 4] = o4;
    }
}

// ---------------- launch ------------------------------------------------------
extern "C" void kernel_launch(void* const* d_in, const int* in_sizes, int n_in,
                              void* d_out, int out_size)
{
    const float* x     = (const float*)d_in[0];
    const float* Wq    = (const float*)d_in[1];
    const float* bq    = (const float*)d_in[2];
    const float* Wk    = (const float*)d_in[3];
    const float* bk    = (const float*)d_in[4];
    const float* Wv    = (const float*)d_in[5];
    const float* bv    = (const float*)d_in[6];
    const float* omega = (const float*)d_in[7];
    float* out = (float*)d_out;

    cudaFuncSetAttribute(k_out, cudaFuncAttributeMaxDynamicSharedMemorySize,
                         K6_SMEM_FLOATS * 4);
    cudaFuncSetAttribute(k_qkv_mma, cudaFuncAttributeMaxDynamicSharedMemorySize,
                         QS_TOTAL);

    k_init<<<1, 1>>>();
    k_split<<<32768, 256>>>(x);
    k_wprep<<<1538, 256>>>(Wq, bq, Wk, bk, Wv, bv);
    k_qkv_mma<<<dim3(3, 256), 256, QS_TOTAL>>>();
    k_aux<<<4128, 256>>>(omega);
    k_pk<<<dim3(256, 2), 256>>>();
    k_ksum<<<dim3(32, 8), 256>>>();
    k_kv<<<dim3(16, 4, 8), 256>>>();
    k_reduce<<<1032, 256>>>();
    k_out<<<dim3(64, 8), 256, K6_SMEM_FLOATS * 4>>>(out);
}